// round 10
// baseline (speedup 1.0000x reference)
#include <cuda_runtime.h>
#include <cstdint>

#define B_    2
#define N_    2048
#define E_    1024
#define H_    16
#define HD_   64
#define MTOT  (B_*N_)          // 4096 rows

// ---------------- scratch (device globals: allocation-guard-safe) ----------
__device__ float g_q[B_*H_*N_*HD_];      // [B,H,N,HD] split layout
__device__ float g_k[B_*H_*N_*HD_];
__device__ float g_v[B_*H_*N_*HD_];      // silu applied
__device__ float g_u[MTOT*E_];           // [B*N, E] flat, silu applied
__device__ float g_attn[B_*H_*N_*HD_];   // attention output, split layout
__device__ float g_g[MTOT*E_];           // gated+normed, flat

// ---------------- packed f32x2 helpers (Blackwell FFMA2) -------------------
__device__ __forceinline__ void ffma2(unsigned long long& d,
                                      unsigned long long a,
                                      unsigned long long b) {
    asm("fma.rn.f32x2 %0, %1, %2, %0;" : "+l"(d) : "l"(a), "l"(b));
}
__device__ __forceinline__ unsigned long long packrep(float x) {
    unsigned long long r; unsigned int u = __float_as_uint(x);
    asm("mov.b64 %0, {%1, %1};" : "=l"(r) : "r"(u));
    return r;
}
__device__ __forceinline__ unsigned long long pack2(float lo, float hi) {
    unsigned long long r;
    asm("mov.b64 %0, {%1, %2};" : "=l"(r)
        : "r"(__float_as_uint(lo)), "r"(__float_as_uint(hi)));
    return r;
}
__device__ __forceinline__ void unpack2(unsigned long long v, float& lo, float& hi) {
    unsigned int a, b;
    asm("mov.b64 {%0, %1}, %2;" : "=r"(a), "=r"(b) : "l"(v));
    lo = __uint_as_float(a); hi = __uint_as_float(b);
}
__device__ __forceinline__ float silu_f(float x) { return x / (1.f + expf(-x)); }

// ---------------------------------------------------------------------------
// SGEMM: out[M=4096, Nc=1024] = A[4096,1024] @ W^T + bias
// W is [out_features, in_features] row-major (torch Linear), so both operands
// are K-major (NT GEMM). 128x128x8 block tile, 256 threads, 8x8 per thread
// (as 8 rows x 4 f32x2 column-pairs).
// modes: 0=q(split) 1=k(split) 2=v(split,silu) 3=u(flat,silu) 4=final(flat)
// ---------------------------------------------------------------------------
__global__ void __launch_bounds__(256, 2) sgemm_kernel(
    const float* __restrict__ A,
    const float* __restrict__ W0, const float* __restrict__ W1,
    const float* __restrict__ W2, const float* __restrict__ W3,
    const float* __restrict__ c0, const float* __restrict__ c1,
    const float* __restrict__ c2, const float* __restrict__ c3,
    float* __restrict__ outp, int mode_base)
{
    const int w    = blockIdx.z;
    const int mode = mode_base + w;
    const float* W    = (w==0)?W0:(w==1)?W1:(w==2)?W2:W3;
    const float* bias = (w==0)?c0:(w==1)?c1:(w==2)?c2:c3;
    const float* Ain  = (mode == 4) ? g_g : A;

    __shared__ __align__(16) float As[8][132];   // As[k][m]
    __shared__ __align__(16) float Bs[8][132];   // Bs[k][j]

    const int tid = threadIdx.x;
    const int tx  = tid & 15;          // column group (j)
    const int ty  = tid >> 4;          // row group (m)
    const int m0  = blockIdx.y * 128;
    const int n0  = blockIdx.x * 128;

    const int lrow = tid >> 1;         // 0..127
    const int lkq  = (tid & 1) * 4;    // 0 or 4

    const float* Aptr = Ain + (size_t)(m0 + lrow) * E_ + lkq;
    const float* Wptr = W   + (size_t)(n0 + lrow) * E_ + lkq;

    unsigned long long acc[8][4];
#pragma unroll
    for (int i = 0; i < 8; i++)
#pragma unroll
        for (int j = 0; j < 4; j++) acc[i][j] = 0ULL;

    for (int k0 = 0; k0 < E_; k0 += 8) {
        float4 av = *(const float4*)(Aptr + k0);
        float4 wv = *(const float4*)(Wptr + k0);
        As[lkq+0][lrow] = av.x; As[lkq+1][lrow] = av.y;
        As[lkq+2][lrow] = av.z; As[lkq+3][lrow] = av.w;
        Bs[lkq+0][lrow] = wv.x; Bs[lkq+1][lrow] = wv.y;
        Bs[lkq+2][lrow] = wv.z; Bs[lkq+3][lrow] = wv.w;
        __syncthreads();
#pragma unroll
        for (int kk = 0; kk < 8; kk++) {
            float4 a0 = *(const float4*)&As[kk][ty*8];
            float4 a1 = *(const float4*)&As[kk][ty*8+4];
            ulonglong2 p0 = *(const ulonglong2*)&Bs[kk][tx*8];
            ulonglong2 p1 = *(const ulonglong2*)&Bs[kk][tx*8+4];
            unsigned long long bv_[4] = {p0.x, p0.y, p1.x, p1.y};
            float a_[8] = {a0.x,a0.y,a0.z,a0.w,a1.x,a1.y,a1.z,a1.w};
#pragma unroll
            for (int i = 0; i < 8; i++) {
                unsigned long long ap = packrep(a_[i]);
#pragma unroll
                for (int j = 0; j < 4; j++) ffma2(acc[i][j], ap, bv_[j]);
            }
        }
        __syncthreads();
    }

    // epilogue
#pragma unroll
    for (int i = 0; i < 8; i++) {
        const int row = m0 + ty*8 + i;
        const int bb  = row >> 11;
        const int nn  = row & (N_ - 1);
#pragma unroll
        for (int j = 0; j < 4; j++) {
            float lo, hi; unpack2(acc[i][j], lo, hi);
            const int col = n0 + tx*8 + j*2;     // even -> col,col+1 same head
            lo += __ldg(&bias[col]);
            hi += __ldg(&bias[col+1]);
            if (mode == 2 || mode == 3) { lo = silu_f(lo); hi = silu_f(hi); }
            if (mode <= 2) {
                float* dst = (mode==0) ? g_q : (mode==1) ? g_k : g_v;
                const int h = col >> 6, d = col & 63;
                const size_t base = (((size_t)bb*H_ + h)*N_ + nn)*HD_ + d;
                dst[base]     = lo;
                dst[base + 1] = hi;
            } else if (mode == 3) {
                g_u[(size_t)row*E_ + col]     = lo;
                g_u[(size_t)row*E_ + col + 1] = hi;
            } else {
                outp[(size_t)row*E_ + col]     = lo;
                outp[(size_t)row*E_ + col + 1] = hi;
            }
        }
    }
}

// ---------------------------------------------------------------------------
// Attention: per (bh, 128-row q tile):
//   acc[128,64] = sum over m-tiles of relu(Q Kt^T / 8) @ Vt
// Q kept transposed in SMEM for the whole block; K transposed / V natural per
// 64-row tile; S staged transposed (Sts[m][n]) between the two GEMM phases.
// ---------------------------------------------------------------------------
#define QS_ST  132
#define KS_ST  68
#define VS_ST  68
#define ST_ST  132
#define SMEM_ATTN ((64*QS_ST + 64*KS_ST + 64*VS_ST + 64*ST_ST) * 4)  // 102400 B

__global__ void __launch_bounds__(256, 2) attn_kernel() {
    extern __shared__ __align__(16) float sm[];
    float* Qs  = sm;                 // [64][132]  (d, n)  -- b-operand phase1
    float* Ks  = Qs + 64*QS_ST;      // [64][68]   (d, m)  -- a-operand phase1
    float* Vs  = Ks + 64*KS_ST;      // [64][68]   (m, d)  -- a-operand phase2
    float* Sts = Vs + 64*VS_ST;      // [64][132]  (m, n)  -- b-operand phase2

    const int bh  = blockIdx.y;
    const int n0  = blockIdx.x * 128;
    const int tid = threadIdx.x;
    const int tx  = tid & 15;
    const int ty  = tid >> 4;
    const size_t base = (size_t)bh * N_ * HD_;
    const float* Qg = g_q + base;
    const float* Kg = g_k + base;
    const float* Vg = g_v + base;

    const int dq = (tid & 15) * 4;   // d quad for loaders
    const int rl = tid >> 4;         // 0..15 row lane for loaders

    // Load Q tile transposed: Qs[d][n_local]
#pragma unroll
    for (int r = 0; r < 8; r++) {
        const int nl = rl + r*16;
        float4 qv = *(const float4*)(Qg + (size_t)(n0 + nl)*HD_ + dq);
        Qs[(dq+0)*QS_ST + nl] = qv.x;
        Qs[(dq+1)*QS_ST + nl] = qv.y;
        Qs[(dq+2)*QS_ST + nl] = qv.z;
        Qs[(dq+3)*QS_ST + nl] = qv.w;
    }

    unsigned long long oacc[4][4];   // [d frag][n pair]
#pragma unroll
    for (int i = 0; i < 4; i++)
#pragma unroll
        for (int j = 0; j < 4; j++) oacc[i][j] = 0ULL;

    for (int mt = 0; mt < N_/64; mt++) {
        const int m0 = mt * 64;
#pragma unroll
        for (int r = 0; r < 4; r++) {
            const int ml = rl + r*16;
            float4 kv = *(const float4*)(Kg + (size_t)(m0+ml)*HD_ + dq);
            Ks[(dq+0)*KS_ST + ml] = kv.x;
            Ks[(dq+1)*KS_ST + ml] = kv.y;
            Ks[(dq+2)*KS_ST + ml] = kv.z;
            Ks[(dq+3)*KS_ST + ml] = kv.w;
            float4 vv = *(const float4*)(Vg + (size_t)(m0+ml)*HD_ + dq);
            *(float4*)&Vs[ml*VS_ST + dq] = vv;
        }
        __syncthreads();

        // ---- phase 1: S[m, n] = Q . K  (K-dim = d = 64) ----
        unsigned long long sacc[4][4];
#pragma unroll
        for (int i = 0; i < 4; i++)
#pragma unroll
            for (int j = 0; j < 4; j++) sacc[i][j] = 0ULL;

#pragma unroll 8
        for (int d = 0; d < 64; d++) {
            float4 a = *(const float4*)&Ks[d*KS_ST + tx*4];
            ulonglong2 q0 = *(const ulonglong2*)&Qs[d*QS_ST + ty*8];
            ulonglong2 q1 = *(const ulonglong2*)&Qs[d*QS_ST + ty*8 + 4];
            unsigned long long bq[4] = {q0.x, q0.y, q1.x, q1.y};
            float aa[4] = {a.x, a.y, a.z, a.w};
#pragma unroll
            for (int mi = 0; mi < 4; mi++) {
                unsigned long long ap = packrep(aa[mi]);
#pragma unroll
                for (int nj = 0; nj < 4; nj++) ffma2(sacc[mi][nj], ap, bq[nj]);
            }
        }

        // scale + relu, stage S transposed
#pragma unroll
        for (int mi = 0; mi < 4; mi++) {
            const int m = tx*4 + mi;
#pragma unroll
            for (int nj = 0; nj < 4; nj++) {
                float lo, hi; unpack2(sacc[mi][nj], lo, hi);
                lo = fmaxf(lo * 0.125f, 0.f);
                hi = fmaxf(hi * 0.125f, 0.f);
                *(unsigned long long*)&Sts[m*ST_ST + ty*8 + nj*2] = pack2(lo, hi);
            }
        }
        __syncthreads();

        // ---- phase 2: acc[n, d] += S[n, m] V[m, d]  (K-dim = m = 64) ----
#pragma unroll 8
        for (int m = 0; m < 64; m++) {
            float4 a = *(const float4*)&Vs[m*VS_ST + tx*4];
            ulonglong2 s0 = *(const ulonglong2*)&Sts[m*ST_ST + ty*8];
            ulonglong2 s1 = *(const ulonglong2*)&Sts[m*ST_ST + ty*8 + 4];
            unsigned long long bs[4] = {s0.x, s0.y, s1.x, s1.y};
            float aa[4] = {a.x, a.y, a.z, a.w};
#pragma unroll
            for (int di = 0; di < 4; di++) {
                unsigned long long ap = packrep(aa[di]);
#pragma unroll
                for (int nj = 0; nj < 4; nj++) ffma2(oacc[di][nj], ap, bs[nj]);
            }
        }
        __syncthreads();
    }

    // write out (split layout)
#pragma unroll
    for (int di = 0; di < 4; di++) {
        const int d = tx*4 + di;
#pragma unroll
        for (int nj = 0; nj < 4; nj++) {
            float lo, hi; unpack2(oacc[di][nj], lo, hi);
            const int n = n0 + ty*8 + nj*2;
            g_attn[base + (size_t)n*HD_ + d]     = lo;
            g_attn[base + (size_t)(n+1)*HD_ + d] = hi;
        }
    }
}

// ---------------------------------------------------------------------------
// LayerNorm (two-pass, matches jnp.var biased) + gate with u
// one block per row; 256 threads x 4 contiguous merged cols each
// ---------------------------------------------------------------------------
__global__ void __launch_bounds__(256) ln_gate_kernel(
    const float* __restrict__ gam, const float* __restrict__ bet)
{
    const int row = blockIdx.x;
    const int bb  = row >> 11;
    const int nn  = row & (N_ - 1);
    const int tid = threadIdx.x;
    const int j0  = tid * 4;
    const int h   = j0 >> 6;
    const int d   = j0 & 63;

    const float* src = g_attn + (((size_t)bb*H_ + h)*N_ + nn)*HD_ + d;
    float4 x = *(const float4*)src;

    __shared__ float red1[8];
    __shared__ float red2[8];

    float s = x.x + x.y + x.z + x.w;
#pragma unroll
    for (int o = 16; o > 0; o >>= 1) s += __shfl_xor_sync(0xffffffffu, s, o);
    if ((tid & 31) == 0) red1[tid >> 5] = s;
    __syncthreads();
    float tot = 0.f;
#pragma unroll
    for (int i = 0; i < 8; i++) tot += red1[i];
    const float mu = tot * (1.f / 1024.f);

    float v0 = x.x - mu, v1 = x.y - mu, v2 = x.z - mu, v3 = x.w - mu;
    float dx = v0*v0 + v1*v1 + v2*v2 + v3*v3;
#pragma unroll
    for (int o = 16; o > 0; o >>= 1) dx += __shfl_xor_sync(0xffffffffu, dx, o);
    if ((tid & 31) == 0) red2[tid >> 5] = dx;
    __syncthreads();
    float tot2 = 0.f;
#pragma unroll
    for (int i = 0; i < 8; i++) tot2 += red2[i];
    const float inv = rsqrtf(tot2 * (1.f / 1024.f) + 1e-5f);

    float4 gv = *(const float4*)(gam + j0);
    float4 bv = *(const float4*)(bet + j0);
    float4 uv = *(const float4*)(g_u + (size_t)row*E_ + j0);
    float4 o4;
    o4.x = uv.x * (v0 * inv * gv.x + bv.x);
    o4.y = uv.y * (v1 * inv * gv.y + bv.y);
    o4.z = uv.z * (v2 * inv * gv.z + bv.z);
    o4.w = uv.w * (v3 * inv * gv.w + bv.w);
    *(float4*)(g_g + (size_t)row*E_ + j0) = o4;
}

// ---------------------------------------------------------------------------
extern "C" void kernel_launch(void* const* d_in, const int* in_sizes, int n_in,
                              void* d_out, int out_size)
{
    (void)in_sizes; (void)n_in; (void)out_size;
    const float* x  = (const float*)d_in[0];
    const float* Wq = (const float*)d_in[1];
    const float* bq = (const float*)d_in[2];
    const float* Wk = (const float*)d_in[3];
    const float* bk = (const float*)d_in[4];
    const float* Wv = (const float*)d_in[5];
    const float* bv = (const float*)d_in[6];
    const float* Wu = (const float*)d_in[7];
    const float* bu = (const float*)d_in[8];
    const float* Wo = (const float*)d_in[9];
    const float* bo = (const float*)d_in[10];
    const float* lg = (const float*)d_in[11];
    const float* lb = (const float*)d_in[12];
    float* out = (float*)d_out;

    cudaFuncSetAttribute(attn_kernel,
                         cudaFuncAttributeMaxDynamicSharedMemorySize, SMEM_ATTN);

    // 1) fused QKVU projections (gridDim.z selects weight + epilogue)
    sgemm_kernel<<<dim3(8, 32, 4), 256>>>(x, Wq, Wk, Wv, Wu,
                                          bq, bk, bv, bu, nullptr, 0);
    // 2) relu-attention
    attn_kernel<<<dim3(16, 32), 256, SMEM_ATTN>>>();
    // 3) layernorm + gate
    ln_gate_kernel<<<MTOT, 256>>>(lg, lb);
    // 4) output projection (reads g_g internally via mode 4)
    sgemm_kernel<<<dim3(8, 32, 1), 256>>>(nullptr, Wo, Wo, Wo, Wo,
                                          bo, bo, bo, bo, out, 4);
}

// round 11
// speedup vs baseline: 1.0020x; 1.0020x over previous
#include <cuda_runtime.h>
#include <cstdint>

#define B_    2
#define N_    2048
#define E_    1024
#define H_    16
#define HD_   64
#define MTOT  (B_*N_)          // 4096 rows

// ---------------- scratch (device globals: allocation-guard-safe) ----------
__device__ float g_q[B_*H_*N_*HD_];      // [B,H,N,HD] split layout
__device__ float g_k[B_*H_*N_*HD_];
__device__ float g_v[B_*H_*N_*HD_];      // silu applied
__device__ float g_u[MTOT*E_];           // [B*N, E] flat, silu applied
__device__ float g_attn[B_*H_*N_*HD_];   // attention output, split layout
__device__ float g_g[MTOT*E_];           // gated+normed, flat

// ---------------- packed f32x2 helpers (Blackwell FFMA2) -------------------
__device__ __forceinline__ void ffma2(unsigned long long& d,
                                      unsigned long long a,
                                      unsigned long long b) {
    asm("fma.rn.f32x2 %0, %1, %2, %0;" : "+l"(d) : "l"(a), "l"(b));
}
__device__ __forceinline__ unsigned long long packrep(float x) {
    unsigned long long r; unsigned int u = __float_as_uint(x);
    asm("mov.b64 %0, {%1, %1};" : "=l"(r) : "r"(u));
    return r;
}
__device__ __forceinline__ unsigned long long pack2(float lo, float hi) {
    unsigned long long r;
    asm("mov.b64 %0, {%1, %2};" : "=l"(r)
        : "r"(__float_as_uint(lo)), "r"(__float_as_uint(hi)));
    return r;
}
__device__ __forceinline__ void unpack2(unsigned long long v, float& lo, float& hi) {
    unsigned int a, b;
    asm("mov.b64 {%0, %1}, %2;" : "=r"(a), "=r"(b) : "l"(v));
    lo = __uint_as_float(a); hi = __uint_as_float(b);
}
__device__ __forceinline__ float silu_f(float x) { return x / (1.f + expf(-x)); }

// ---------------------------------------------------------------------------
// SGEMM: out[M=4096, Nc=1024] = A[4096,1024] @ W^T + bias
// W is [out_features, in_features] row-major (torch Linear), so both operands
// are K-major (NT GEMM). 128x128x8 block tile, 256 threads, 8x8 per thread
// (as 8 rows x 4 f32x2 column-pairs).
// modes: 0=q(split) 1=k(split) 2=v(split,silu) 3=u(flat,silu) 4=final(flat)
// ---------------------------------------------------------------------------
__global__ void __launch_bounds__(256, 2) sgemm_kernel(
    const float* __restrict__ A,
    const float* __restrict__ W0, const float* __restrict__ W1,
    const float* __restrict__ W2, const float* __restrict__ W3,
    const float* __restrict__ c0, const float* __restrict__ c1,
    const float* __restrict__ c2, const float* __restrict__ c3,
    float* __restrict__ outp, int mode_base)
{
    const int w    = blockIdx.z;
    const int mode = mode_base + w;
    const float* W    = (w==0)?W0:(w==1)?W1:(w==2)?W2:W3;
    const float* bias = (w==0)?c0:(w==1)?c1:(w==2)?c2:c3;
    const float* Ain  = (mode == 4) ? g_g : A;

    __shared__ __align__(16) float As[8][132];   // As[k][m]
    __shared__ __align__(16) float Bs[8][132];   // Bs[k][j]

    const int tid = threadIdx.x;
    const int tx  = tid & 15;          // column group (j)
    const int ty  = tid >> 4;          // row group (m)
    const int m0  = blockIdx.y * 128;
    const int n0  = blockIdx.x * 128;

    const int lrow = tid >> 1;         // 0..127
    const int lkq  = (tid & 1) * 4;    // 0 or 4

    const float* Aptr = Ain + (size_t)(m0 + lrow) * E_ + lkq;
    const float* Wptr = W   + (size_t)(n0 + lrow) * E_ + lkq;

    unsigned long long acc[8][4];
#pragma unroll
    for (int i = 0; i < 8; i++)
#pragma unroll
        for (int j = 0; j < 4; j++) acc[i][j] = 0ULL;

    for (int k0 = 0; k0 < E_; k0 += 8) {
        float4 av = *(const float4*)(Aptr + k0);
        float4 wv = *(const float4*)(Wptr + k0);
        As[lkq+0][lrow] = av.x; As[lkq+1][lrow] = av.y;
        As[lkq+2][lrow] = av.z; As[lkq+3][lrow] = av.w;
        Bs[lkq+0][lrow] = wv.x; Bs[lkq+1][lrow] = wv.y;
        Bs[lkq+2][lrow] = wv.z; Bs[lkq+3][lrow] = wv.w;
        __syncthreads();
#pragma unroll
        for (int kk = 0; kk < 8; kk++) {
            float4 a0 = *(const float4*)&As[kk][ty*8];
            float4 a1 = *(const float4*)&As[kk][ty*8+4];
            ulonglong2 p0 = *(const ulonglong2*)&Bs[kk][tx*8];
            ulonglong2 p1 = *(const ulonglong2*)&Bs[kk][tx*8+4];
            unsigned long long bv_[4] = {p0.x, p0.y, p1.x, p1.y};
            float a_[8] = {a0.x,a0.y,a0.z,a0.w,a1.x,a1.y,a1.z,a1.w};
#pragma unroll
            for (int i = 0; i < 8; i++) {
                unsigned long long ap = packrep(a_[i]);
#pragma unroll
                for (int j = 0; j < 4; j++) ffma2(acc[i][j], ap, bv_[j]);
            }
        }
        __syncthreads();
    }

    // epilogue
#pragma unroll
    for (int i = 0; i < 8; i++) {
        const int row = m0 + ty*8 + i;
        const int bb  = row >> 11;
        const int nn  = row & (N_ - 1);
#pragma unroll
        for (int j = 0; j < 4; j++) {
            float lo, hi; unpack2(acc[i][j], lo, hi);
            const int col = n0 + tx*8 + j*2;     // even -> col,col+1 same head
            lo += __ldg(&bias[col]);
            hi += __ldg(&bias[col+1]);
            if (mode == 2 || mode == 3) { lo = silu_f(lo); hi = silu_f(hi); }
            if (mode <= 2) {
                float* dst = (mode==0) ? g_q : (mode==1) ? g_k : g_v;
                const int h = col >> 6, d = col & 63;
                const size_t base = (((size_t)bb*H_ + h)*N_ + nn)*HD_ + d;
                dst[base]     = lo;
                dst[base + 1] = hi;
            } else if (mode == 3) {
                g_u[(size_t)row*E_ + col]     = lo;
                g_u[(size_t)row*E_ + col + 1] = hi;
            } else {
                outp[(size_t)row*E_ + col]     = lo;
                outp[(size_t)row*E_ + col + 1] = hi;
            }
        }
    }
}

// ---------------------------------------------------------------------------
// Attention: per (bh, 128-row q tile):
//   acc[128,64] = sum over m-tiles of relu(Q Kt^T / 8) @ Vt
// Q kept transposed in SMEM for the whole block; K transposed / V natural per
// 64-row tile; S staged transposed (Sts[m][n]) between the two GEMM phases.
// ---------------------------------------------------------------------------
#define QS_ST  132
#define KS_ST  68
#define VS_ST  68
#define ST_ST  132
#define SMEM_ATTN ((64*QS_ST + 64*KS_ST + 64*VS_ST + 64*ST_ST) * 4)  // 102400 B

__global__ void __launch_bounds__(256, 2) attn_kernel() {
    extern __shared__ __align__(16) float sm[];
    float* Qs  = sm;                 // [64][132]  (d, n)  -- b-operand phase1
    float* Ks  = Qs + 64*QS_ST;      // [64][68]   (d, m)  -- a-operand phase1
    float* Vs  = Ks + 64*KS_ST;      // [64][68]   (m, d)  -- a-operand phase2
    float* Sts = Vs + 64*VS_ST;      // [64][132]  (m, n)  -- b-operand phase2

    const int bh  = blockIdx.y;
    const int n0  = blockIdx.x * 128;
    const int tid = threadIdx.x;
    const int tx  = tid & 15;
    const int ty  = tid >> 4;
    const size_t base = (size_t)bh * N_ * HD_;
    const float* Qg = g_q + base;
    const float* Kg = g_k + base;
    const float* Vg = g_v + base;

    const int dq = (tid & 15) * 4;   // d quad for loaders
    const int rl = tid >> 4;         // 0..15 row lane for loaders

    // Load Q tile transposed: Qs[d][n_local]
#pragma unroll
    for (int r = 0; r < 8; r++) {
        const int nl = rl + r*16;
        float4 qv = *(const float4*)(Qg + (size_t)(n0 + nl)*HD_ + dq);
        Qs[(dq+0)*QS_ST + nl] = qv.x;
        Qs[(dq+1)*QS_ST + nl] = qv.y;
        Qs[(dq+2)*QS_ST + nl] = qv.z;
        Qs[(dq+3)*QS_ST + nl] = qv.w;
    }

    unsigned long long oacc[4][4];   // [d frag][n pair]
#pragma unroll
    for (int i = 0; i < 4; i++)
#pragma unroll
        for (int j = 0; j < 4; j++) oacc[i][j] = 0ULL;

    for (int mt = 0; mt < N_/64; mt++) {
        const int m0 = mt * 64;
#pragma unroll
        for (int r = 0; r < 4; r++) {
            const int ml = rl + r*16;
            float4 kv = *(const float4*)(Kg + (size_t)(m0+ml)*HD_ + dq);
            Ks[(dq+0)*KS_ST + ml] = kv.x;
            Ks[(dq+1)*KS_ST + ml] = kv.y;
            Ks[(dq+2)*KS_ST + ml] = kv.z;
            Ks[(dq+3)*KS_ST + ml] = kv.w;
            float4 vv = *(const float4*)(Vg + (size_t)(m0+ml)*HD_ + dq);
            *(float4*)&Vs[ml*VS_ST + dq] = vv;
        }
        __syncthreads();

        // ---- phase 1: S[m, n] = Q . K  (K-dim = d = 64) ----
        unsigned long long sacc[4][4];
#pragma unroll
        for (int i = 0; i < 4; i++)
#pragma unroll
            for (int j = 0; j < 4; j++) sacc[i][j] = 0ULL;

#pragma unroll 8
        for (int d = 0; d < 64; d++) {
            float4 a = *(const float4*)&Ks[d*KS_ST + tx*4];
            ulonglong2 q0 = *(const ulonglong2*)&Qs[d*QS_ST + ty*8];
            ulonglong2 q1 = *(const ulonglong2*)&Qs[d*QS_ST + ty*8 + 4];
            unsigned long long bq[4] = {q0.x, q0.y, q1.x, q1.y};
            float aa[4] = {a.x, a.y, a.z, a.w};
#pragma unroll
            for (int mi = 0; mi < 4; mi++) {
                unsigned long long ap = packrep(aa[mi]);
#pragma unroll
                for (int nj = 0; nj < 4; nj++) ffma2(sacc[mi][nj], ap, bq[nj]);
            }
        }

        // scale + relu, stage S transposed
#pragma unroll
        for (int mi = 0; mi < 4; mi++) {
            const int m = tx*4 + mi;
#pragma unroll
            for (int nj = 0; nj < 4; nj++) {
                float lo, hi; unpack2(sacc[mi][nj], lo, hi);
                lo = fmaxf(lo * 0.125f, 0.f);
                hi = fmaxf(hi * 0.125f, 0.f);
                *(unsigned long long*)&Sts[m*ST_ST + ty*8 + nj*2] = pack2(lo, hi);
            }
        }
        __syncthreads();

        // ---- phase 2: acc[n, d] += S[n, m] V[m, d]  (K-dim = m = 64) ----
#pragma unroll 8
        for (int m = 0; m < 64; m++) {
            float4 a = *(const float4*)&Vs[m*VS_ST + tx*4];
            ulonglong2 s0 = *(const ulonglong2*)&Sts[m*ST_ST + ty*8];
            ulonglong2 s1 = *(const ulonglong2*)&Sts[m*ST_ST + ty*8 + 4];
            unsigned long long bs[4] = {s0.x, s0.y, s1.x, s1.y};
            float aa[4] = {a.x, a.y, a.z, a.w};
#pragma unroll
            for (int di = 0; di < 4; di++) {
                unsigned long long ap = packrep(aa[di]);
#pragma unroll
                for (int nj = 0; nj < 4; nj++) ffma2(oacc[di][nj], ap, bs[nj]);
            }
        }
        __syncthreads();
    }

    // write out (split layout)
#pragma unroll
    for (int di = 0; di < 4; di++) {
        const int d = tx*4 + di;
#pragma unroll
        for (int nj = 0; nj < 4; nj++) {
            float lo, hi; unpack2(oacc[di][nj], lo, hi);
            const int n = n0 + ty*8 + nj*2;
            g_attn[base + (size_t)n*HD_ + d]     = lo;
            g_attn[base + (size_t)(n+1)*HD_ + d] = hi;
        }
    }
}

// ---------------------------------------------------------------------------
// LayerNorm (two-pass, matches jnp.var biased) + gate with u
// one block per row; 256 threads x 4 contiguous merged cols each
// ---------------------------------------------------------------------------
__global__ void __launch_bounds__(256) ln_gate_kernel(
    const float* __restrict__ gam, const float* __restrict__ bet)
{
    const int row = blockIdx.x;
    const int bb  = row >> 11;
    const int nn  = row & (N_ - 1);
    const int tid = threadIdx.x;
    const int j0  = tid * 4;
    const int h   = j0 >> 6;
    const int d   = j0 & 63;

    const float* src = g_attn + (((size_t)bb*H_ + h)*N_ + nn)*HD_ + d;
    float4 x = *(const float4*)src;

    __shared__ float red1[8];
    __shared__ float red2[8];

    float s = x.x + x.y + x.z + x.w;
#pragma unroll
    for (int o = 16; o > 0; o >>= 1) s += __shfl_xor_sync(0xffffffffu, s, o);
    if ((tid & 31) == 0) red1[tid >> 5] = s;
    __syncthreads();
    float tot = 0.f;
#pragma unroll
    for (int i = 0; i < 8; i++) tot += red1[i];
    const float mu = tot * (1.f / 1024.f);

    float v0 = x.x - mu, v1 = x.y - mu, v2 = x.z - mu, v3 = x.w - mu;
    float dx = v0*v0 + v1*v1 + v2*v2 + v3*v3;
#pragma unroll
    for (int o = 16; o > 0; o >>= 1) dx += __shfl_xor_sync(0xffffffffu, dx, o);
    if ((tid & 31) == 0) red2[tid >> 5] = dx;
    __syncthreads();
    float tot2 = 0.f;
#pragma unroll
    for (int i = 0; i < 8; i++) tot2 += red2[i];
    const float inv = rsqrtf(tot2 * (1.f / 1024.f) + 1e-5f);

    float4 gv = *(const float4*)(gam + j0);
    float4 bv = *(const float4*)(bet + j0);
    float4 uv = *(const float4*)(g_u + (size_t)row*E_ + j0);
    float4 o4;
    o4.x = uv.x * (v0 * inv * gv.x + bv.x);
    o4.y = uv.y * (v1 * inv * gv.y + bv.y);
    o4.z = uv.z * (v2 * inv * gv.z + bv.z);
    o4.w = uv.w * (v3 * inv * gv.w + bv.w);
    *(float4*)(g_g + (size_t)row*E_ + j0) = o4;
}

// ---------------------------------------------------------------------------
extern "C" void kernel_launch(void* const* d_in, const int* in_sizes, int n_in,
                              void* d_out, int out_size)
{
    (void)in_sizes; (void)n_in; (void)out_size;
    const float* x  = (const float*)d_in[0];
    const float* Wq = (const float*)d_in[1];
    const float* bq = (const float*)d_in[2];
    const float* Wk = (const float*)d_in[3];
    const float* bk = (const float*)d_in[4];
    const float* Wv = (const float*)d_in[5];
    const float* bv = (const float*)d_in[6];
    const float* Wu = (const float*)d_in[7];
    const float* bu = (const float*)d_in[8];
    const float* Wo = (const float*)d_in[9];
    const float* bo = (const float*)d_in[10];
    const float* lg = (const float*)d_in[11];
    const float* lb = (const float*)d_in[12];
    float* out = (float*)d_out;

    cudaFuncSetAttribute(attn_kernel,
                         cudaFuncAttributeMaxDynamicSharedMemorySize, SMEM_ATTN);

    // 1) fused QKVU projections (gridDim.z selects weight + epilogue)
    sgemm_kernel<<<dim3(8, 32, 4), 256>>>(x, Wq, Wk, Wv, Wu,
                                          bq, bk, bv, bu, nullptr, 0);
    // 2) relu-attention
    attn_kernel<<<dim3(16, 32), 256, SMEM_ATTN>>>();
    // 3) layernorm + gate
    ln_gate_kernel<<<MTOT, 256>>>(lg, lb);
    // 4) output projection (reads g_g internally via mode 4)
    sgemm_kernel<<<dim3(8, 32, 1), 256>>>(nullptr, Wo, Wo, Wo, Wo,
                                          bo, bo, bo, bo, out, 4);
}